// round 14
// baseline (speedup 1.0000x reference)
#include <cuda_runtime.h>
#include <cuda_bf16.h>
#include <cuda_fp16.h>
#include <cstdint>

#define N_NODES_MAX 50048
#define E_MAX 1600000
#define DIM 128
#define BCAP 128
#define BN_EPS 1e-5f

// ---------------- device scratch ----------------
__device__ __half g_h[N_NODES_MAX * DIM];     // x @ W fp16; scaled in-place to h*dinv
__device__ __half g_agg[N_NODES_MAX * DIM];   // aggregated messages (fp16)
__device__ float g_dinv[N_NODES_MAX];
__device__ int   g_cnt[N_NODES_MAX];          // zero at module load; re-zeroed by out_kernel
__device__ int   g_bkt[N_NODES_MAX * BCAP];   // per-node edge buckets
__device__ float g_stats[2 * DIM];

// ---------------- stream/event fork-join resources (static init) ------
struct ForkRes {
    cudaStream_t s;
    cudaEvent_t e0, e1;
    ForkRes() {
        cudaStreamCreateWithFlags(&s, cudaStreamNonBlocking);
        cudaEventCreateWithFlags(&e0, cudaEventDisableTiming);
        cudaEventCreateWithFlags(&e1, cudaEventDisableTiming);
    }
};
static ForkRes g_fork;

// ---------------- bucket fill: single edge pass ----------------
__global__ void fill_kernel(const int* __restrict__ src,
                            const int* __restrict__ dst, int E) {
    int e = blockIdx.x * blockDim.x + threadIdx.x;
    if (e < E) {
        int d = dst[e];
        int pos = atomicAdd(&g_cnt[d], 1);
        if (pos < BCAP)
            g_bkt[(size_t)d * BCAP + pos] = src[e];
    }
}

// ---------------- dinv from counts (+ zero stats for this pass) -------
__global__ void dinv_kernel(int n) {
    int i = blockIdx.x * blockDim.x + threadIdx.x;
    if (i < n) g_dinv[i] = rsqrtf((float)(g_cnt[i] + 1));
    if (i < 2 * DIM) g_stats[i] = 0.0f;
}

// ---------------- pre-scale: h *= dinv[row] (in-place, once/replay) ---
__global__ __launch_bounds__(256) void scale_kernel(int total2) {
    int i = blockIdx.x * blockDim.x + threadIdx.x;   // one uint2 = 4 halves
    if (i >= total2) return;
    int row = i >> 5;                                 // 32 uint2 per row
    float di = g_dinv[row];
    uint2 raw = *((uint2*)g_h + i);
    float2 f0 = __half22float2(*(__half2*)&raw.x);
    float2 f1 = __half22float2(*(__half2*)&raw.y);
    uint2 packed;
    *(__half2*)&packed.x = __floats2half2_rn(f0.x * di, f0.y * di);
    *(__half2*)&packed.y = __floats2half2_rn(f1.x * di, f1.y * di);
    *((uint2*)g_h + i) = packed;
}

// ---------------- single-pass TF32 tensor-core GEMM: h = x @ W --------
__device__ __forceinline__ uint32_t to_tf32(float v) {
    uint32_t h;
    asm("cvt.rna.tf32.f32 %0, %1;" : "=r"(h) : "f"(v));
    return h;
}

__device__ __forceinline__ void mma_tf32(float* c, uint32_t a0, uint32_t a1,
                                         uint32_t a2, uint32_t a3,
                                         uint32_t b0, uint32_t b1) {
    asm volatile(
        "mma.sync.aligned.m16n8k8.row.col.f32.tf32.tf32.f32 "
        "{%0,%1,%2,%3}, {%4,%5,%6,%7}, {%8,%9}, {%0,%1,%2,%3};"
        : "+f"(c[0]), "+f"(c[1]), "+f"(c[2]), "+f"(c[3])
        : "r"(a0), "r"(a1), "r"(a2), "r"(a3), "r"(b0), "r"(b1));
}

#define KC 32
__global__ __launch_bounds__(256, 2) void gemm_tc_kernel(
    const float* __restrict__ x, const float* __restrict__ W, int n)
{
    __shared__ float xs[128][36];
    __shared__ float ws[KC][132];

    const int t = threadIdx.x;
    const int wid = t >> 5, lane = t & 31;
    const int rowg = wid & 3, colg = wid >> 2;
    const int g = lane >> 2, t4 = lane & 3;
    const int row0 = blockIdx.x * 128;

    float acc[2][8][4];
#pragma unroll
    for (int mi = 0; mi < 2; mi++)
#pragma unroll
        for (int nt = 0; nt < 8; nt++)
#pragma unroll
            for (int c = 0; c < 4; c++) acc[mi][nt][c] = 0.f;

    for (int kc = 0; kc < DIM; kc += KC) {
        for (int idx = t; idx < 1024; idx += 256) {
            int r = idx >> 3, k4 = (idx & 7) << 2;
            int row = row0 + r;
            float4 v = make_float4(0.f, 0.f, 0.f, 0.f);
            if (row < n) v = *(const float4*)(x + (size_t)row * DIM + kc + k4);
            *(float4*)&xs[r][k4] = v;
        }
        for (int idx = t; idx < 1024; idx += 256) {
            int k = idx >> 5, n4 = (idx & 31) << 2;
            *(float4*)&ws[k][n4] = *(const float4*)(W + (size_t)(kc + k) * DIM + n4);
        }
        __syncthreads();

#pragma unroll
        for (int ks = 0; ks < KC; ks += 8) {
            uint32_t a[2][4];
#pragma unroll
            for (int mi = 0; mi < 2; mi++) {
                int rb = rowg * 32 + mi * 16;
                a[mi][0] = to_tf32(xs[rb + g][ks + t4]);
                a[mi][1] = to_tf32(xs[rb + g + 8][ks + t4]);
                a[mi][2] = to_tf32(xs[rb + g][ks + t4 + 4]);
                a[mi][3] = to_tf32(xs[rb + g + 8][ks + t4 + 4]);
            }
#pragma unroll
            for (int nt = 0; nt < 8; nt++) {
                int cb = colg * 64 + nt * 8;
                uint32_t b0 = to_tf32(ws[ks + t4][cb + g]);
                uint32_t b1 = to_tf32(ws[ks + t4 + 4][cb + g]);
#pragma unroll
                for (int mi = 0; mi < 2; mi++)
                    mma_tf32(acc[mi][nt], a[mi][0], a[mi][1], a[mi][2], a[mi][3], b0, b1);
            }
        }
        __syncthreads();
    }

#pragma unroll
    for (int mi = 0; mi < 2; mi++) {
        int rb = row0 + rowg * 32 + mi * 16;
#pragma unroll
        for (int nt = 0; nt < 8; nt++) {
            int col = colg * 64 + nt * 8 + 2 * t4;
            int r0 = rb + g, r1 = rb + g + 8;
            if (r0 < n)
                *(__half2*)(g_h + (size_t)r0 * DIM + col) =
                    __floats2half2_rn(acc[mi][nt][0], acc[mi][nt][1]);
            if (r1 < n)
                *(__half2*)(g_h + (size_t)r1 * DIM + col) =
                    __floats2half2_rn(acc[mi][nt][2], acc[mi][nt][3]);
        }
    }
}

// ---------------- per-node accumulate + fused BN stats ----------------
// inner loop: pure unscaled row adds (h already pre-scaled by dinv[src])
__device__ __forceinline__ void add_row(float4& s, uint2 raw) {
    float2 f0 = __half22float2(*(__half2*)&raw.x);
    float2 f1 = __half22float2(*(__half2*)&raw.y);
    s.x += f0.x; s.y += f0.y; s.z += f1.x; s.w += f1.y;
}

__global__ __launch_bounds__(256) void acc_kernel(const float* __restrict__ b, int n)
{
    __shared__ float ssum[8][128];
    __shared__ float ssq[8][128];
    const int w = (blockIdx.x * blockDim.x + threadIdx.x) >> 5;
    const int wid = threadIdx.x >> 5;
    const int lane = threadIdx.x & 31;

    float4 acc = make_float4(0.f, 0.f, 0.f, 0.f);
    if (w < n) {
        float di = g_dinv[w];
        // sum of pre-scaled rows: self + neighbors
        float4 sum = make_float4(0.f, 0.f, 0.f, 0.f);
        {
            uint2 raw = __ldg((const uint2*)(g_h + (size_t)w * DIM) + lane);
            add_row(sum, raw);
        }
        const int cnt = g_cnt[w];
        const int* bkt = g_bkt + (size_t)w * BCAP;
        int j = 0;
        for (; j + 4 <= cnt; j += 4) {
            int s0 = __ldg(bkt + j);
            int s1 = __ldg(bkt + j + 1);
            int s2 = __ldg(bkt + j + 2);
            int s3 = __ldg(bkt + j + 3);
            uint2 r0 = __ldg((const uint2*)(g_h + (size_t)s0 * DIM) + lane);
            uint2 r1 = __ldg((const uint2*)(g_h + (size_t)s1 * DIM) + lane);
            uint2 r2 = __ldg((const uint2*)(g_h + (size_t)s2 * DIM) + lane);
            uint2 r3 = __ldg((const uint2*)(g_h + (size_t)s3 * DIM) + lane);
            add_row(sum, r0);
            add_row(sum, r1);
            add_row(sum, r2);
            add_row(sum, r3);
        }
        for (; j < cnt; j++) {
            int s0 = __ldg(bkt + j);
            uint2 r0 = __ldg((const uint2*)(g_h + (size_t)s0 * DIM) + lane);
            add_row(sum, r0);
        }
        // agg = b + dinv[d] * sum
        float4 bv = __ldg((const float4*)b + lane);
        acc.x = bv.x + di * sum.x;
        acc.y = bv.y + di * sum.y;
        acc.z = bv.z + di * sum.z;
        acc.w = bv.w + di * sum.w;
        // store agg as fp16 (stats below use the fp32 registers)
        uint2 packed;
        *(__half2*)&packed.x = __floats2half2_rn(acc.x, acc.y);
        *(__half2*)&packed.y = __floats2half2_rn(acc.z, acc.w);
        *((uint2*)(g_agg + (size_t)w * DIM) + lane) = packed;
    }
    *(float4*)&ssum[wid][lane * 4] = acc;
    float4 sq = make_float4(acc.x * acc.x, acc.y * acc.y, acc.z * acc.z, acc.w * acc.w);
    *(float4*)&ssq[wid][lane * 4] = sq;
    __syncthreads();

    int t = threadIdx.x;
    if (t < 128) {
        float s = 0.f;
#pragma unroll
        for (int k = 0; k < 8; k++) s += ssum[k][t];
        atomicAdd(&g_stats[t], s);
    } else {
        int d = t - 128;
        float s = 0.f;
#pragma unroll
        for (int k = 0; k < 8; k++) s += ssq[k][d];
        atomicAdd(&g_stats[DIM + d], s);
    }
}

// ---------------- epilogue: finalize fused, relu(BN(agg)) + x ---------
// also re-zeroes g_cnt for the next invocation (globals start zeroed at load)
__global__ __launch_bounds__(256) void out_kernel(
    const float* __restrict__ x, const float* __restrict__ gamma,
    const float* __restrict__ beta, float* __restrict__ out,
    float inv_n, int total4, int n)
{
    __shared__ float ssc[DIM];
    __shared__ float ssh[DIM];
    int t = threadIdx.x;
    if (t < DIM) {
        float mean = g_stats[t] * inv_n;
        float var  = g_stats[DIM + t] * inv_n - mean * mean;
        float sc = gamma[t] * rsqrtf(var + BN_EPS);
        ssc[t] = sc;
        ssh[t] = beta[t] - mean * sc;
    }
    __syncthreads();

    int i = blockIdx.x * blockDim.x + t;
    if (i < n) g_cnt[i] = 0;               // reset for next replay
    if (i >= total4) return;
    int d4 = i & 31;
    uint2 raw = ((const uint2*)g_agg)[i];
    float2 a01 = __half22float2(*(__half2*)&raw.x);
    float2 a23 = __half22float2(*(__half2*)&raw.y);
    float4 sc = *(float4*)&ssc[d4 * 4];
    float4 sh = *(float4*)&ssh[d4 * 4];
    float4 xv = ((const float4*)x)[i];
    float4 y;
    y.x = fmaxf(a01.x * sc.x + sh.x, 0.f) + xv.x;
    y.y = fmaxf(a01.y * sc.y + sh.y, 0.f) + xv.y;
    y.z = fmaxf(a23.x * sc.z + sh.z, 0.f) + xv.z;
    y.w = fmaxf(a23.y * sc.w + sh.w, 0.f) + xv.w;
    ((float4*)out)[i] = y;
}

// ---------------- launch ----------------------------------------------
extern "C" void kernel_launch(void* const* d_in, const int* in_sizes, int n_in,
                              void* d_out, int out_size)
{
    const float* x     = (const float*)d_in[0];
    const float* W     = (const float*)d_in[1];
    const float* b     = (const float*)d_in[2];
    const float* gamma = (const float*)d_in[3];
    const float* beta  = (const float*)d_in[4];
    const int*   ei    = (const int*)d_in[5];

    const int n = in_sizes[0] / DIM;
    const int E = in_sizes[5] / 2;
    const int* src = ei;
    const int* dst = ei + E;

    // fork: GEMM on side stream, overlapping the bucket build
    cudaEventRecord(g_fork.e0, 0);
    cudaStreamWaitEvent(g_fork.s, g_fork.e0, 0);
    gemm_tc_kernel<<<(n + 127) / 128, 256, 0, g_fork.s>>>(x, W, n);
    cudaEventRecord(g_fork.e1, g_fork.s);

    // main chain: single-pass bucket CSR
    fill_kernel<<<(E + 255) / 256, 256>>>(src, dst, E);
    dinv_kernel<<<(n + 255) / 256, 256>>>(n);   // also zeroes stats

    // join, then pre-scale h by dinv (needs both GEMM h and dinv)
    cudaStreamWaitEvent(0, g_fork.e1, 0);
    int total2 = n * DIM / 4;
    scale_kernel<<<(total2 + 255) / 256, 256>>>(total2);

    acc_kernel<<<(n + 7) / 8, 256>>>(b, n);

    int total4 = n * DIM / 4;
    out_kernel<<<(total4 + 255) / 256, 256>>>(x, gamma, beta, (float*)d_out,
                                              1.0f / (float)n, total4, n);
}

// round 15
// speedup vs baseline: 1.0139x; 1.0139x over previous
#include <cuda_runtime.h>
#include <cuda_bf16.h>
#include <cuda_fp16.h>
#include <cstdint>

#define N_NODES_MAX 50048
#define E_MAX 1600000
#define DIM 128
#define BCAP 128
#define BN_EPS 1e-5f

// ---------------- device scratch ----------------
__device__ __half g_h[N_NODES_MAX * DIM];     // x @ W in fp16 (gather payload)
__device__ __half g_agg[N_NODES_MAX * DIM];   // aggregated messages (fp16)
__device__ float g_dinv[N_NODES_MAX];
__device__ int   g_cnt[N_NODES_MAX];          // zero at module load; re-zeroed by out_kernel
__device__ int   g_bkt[N_NODES_MAX * BCAP];   // per-node edge buckets
__device__ float g_stats[2 * DIM];

// ---------------- stream/event fork-join resources (static init) ------
struct ForkRes {
    cudaStream_t s;
    cudaEvent_t e0, e1;
    ForkRes() {
        cudaStreamCreateWithFlags(&s, cudaStreamNonBlocking);
        cudaEventCreateWithFlags(&e0, cudaEventDisableTiming);
        cudaEventCreateWithFlags(&e1, cudaEventDisableTiming);
    }
};
static ForkRes g_fork;

// ---------------- bucket fill: single edge pass ----------------
__global__ void fill_kernel(const int* __restrict__ src,
                            const int* __restrict__ dst, int E) {
    int e = blockIdx.x * blockDim.x + threadIdx.x;
    if (e < E) {
        int d = dst[e];
        int pos = atomicAdd(&g_cnt[d], 1);
        if (pos < BCAP)
            g_bkt[(size_t)d * BCAP + pos] = src[e];
    }
}

// ---------------- dinv from counts (+ zero stats for this pass) -------
__global__ void dinv_kernel(int n) {
    int i = blockIdx.x * blockDim.x + threadIdx.x;
    if (i < n) g_dinv[i] = rsqrtf((float)(g_cnt[i] + 1));
    if (i < 2 * DIM) g_stats[i] = 0.0f;
}

// ---------------- single-pass TF32 GEMM, staging-time conversion ------
__device__ __forceinline__ uint32_t to_tf32(float v) {
    uint32_t h;
    asm("cvt.rna.tf32.f32 %0, %1;" : "=r"(h) : "f"(v));
    return h;
}

__device__ __forceinline__ void mma_tf32(float* c, uint32_t a0, uint32_t a1,
                                         uint32_t a2, uint32_t a3,
                                         uint32_t b0, uint32_t b1) {
    asm volatile(
        "mma.sync.aligned.m16n8k8.row.col.f32.tf32.tf32.f32 "
        "{%0,%1,%2,%3}, {%4,%5,%6,%7}, {%8,%9}, {%0,%1,%2,%3};"
        : "+f"(c[0]), "+f"(c[1]), "+f"(c[2]), "+f"(c[3])
        : "r"(a0), "r"(a1), "r"(a2), "r"(a3), "r"(b0), "r"(b1));
}

#define KC 32
__global__ __launch_bounds__(256, 2) void gemm_tc_kernel(
    const float* __restrict__ x, const float* __restrict__ W, int n)
{
    __shared__ uint32_t xs[128][36];   // tf32 bit patterns
    __shared__ uint32_t ws[KC][132];

    const int t = threadIdx.x;
    const int wid = t >> 5, lane = t & 31;
    const int rowg = wid & 3, colg = wid >> 2;
    const int g = lane >> 2, t4 = lane & 3;
    const int row0 = blockIdx.x * 128;

    float acc[2][8][4];
#pragma unroll
    for (int mi = 0; mi < 2; mi++)
#pragma unroll
        for (int nt = 0; nt < 8; nt++)
#pragma unroll
            for (int c = 0; c < 4; c++) acc[mi][nt][c] = 0.f;

    for (int kc = 0; kc < DIM; kc += KC) {
        for (int idx = t; idx < 1024; idx += 256) {
            int r = idx >> 3, k4 = (idx & 7) << 2;
            int row = row0 + r;
            float4 v = make_float4(0.f, 0.f, 0.f, 0.f);
            if (row < n) v = *(const float4*)(x + (size_t)row * DIM + kc + k4);
            xs[r][k4 + 0] = to_tf32(v.x);
            xs[r][k4 + 1] = to_tf32(v.y);
            xs[r][k4 + 2] = to_tf32(v.z);
            xs[r][k4 + 3] = to_tf32(v.w);
        }
        for (int idx = t; idx < 1024; idx += 256) {
            int k = idx >> 5, n4 = (idx & 31) << 2;
            float4 v = *(const float4*)(W + (size_t)(kc + k) * DIM + n4);
            ws[k][n4 + 0] = to_tf32(v.x);
            ws[k][n4 + 1] = to_tf32(v.y);
            ws[k][n4 + 2] = to_tf32(v.z);
            ws[k][n4 + 3] = to_tf32(v.w);
        }
        __syncthreads();

#pragma unroll
        for (int ks = 0; ks < KC; ks += 8) {
            uint32_t a[2][4];
#pragma unroll
            for (int mi = 0; mi < 2; mi++) {
                int rb = rowg * 32 + mi * 16;
                a[mi][0] = xs[rb + g][ks + t4];
                a[mi][1] = xs[rb + g + 8][ks + t4];
                a[mi][2] = xs[rb + g][ks + t4 + 4];
                a[mi][3] = xs[rb + g + 8][ks + t4 + 4];
            }
#pragma unroll
            for (int nt = 0; nt < 8; nt++) {
                int cb = colg * 64 + nt * 8;
                uint32_t b0 = ws[ks + t4][cb + g];
                uint32_t b1 = ws[ks + t4 + 4][cb + g];
#pragma unroll
                for (int mi = 0; mi < 2; mi++)
                    mma_tf32(acc[mi][nt], a[mi][0], a[mi][1], a[mi][2], a[mi][3], b0, b1);
            }
        }
        __syncthreads();
    }

#pragma unroll
    for (int mi = 0; mi < 2; mi++) {
        int rb = row0 + rowg * 32 + mi * 16;
#pragma unroll
        for (int nt = 0; nt < 8; nt++) {
            int col = colg * 64 + nt * 8 + 2 * t4;
            int r0 = rb + g, r1 = rb + g + 8;
            if (r0 < n)
                *(__half2*)(g_h + (size_t)r0 * DIM + col) =
                    __floats2half2_rn(acc[mi][nt][0], acc[mi][nt][1]);
            if (r1 < n)
                *(__half2*)(g_h + (size_t)r1 * DIM + col) =
                    __floats2half2_rn(acc[mi][nt][2], acc[mi][nt][3]);
        }
    }
}

// ---------------- per-node accumulate + fused BN stats ----------------
__device__ __forceinline__ void fma_row(float4& acc, uint2 raw, float nm) {
    __half2 p0 = *(__half2*)&raw.x, p1 = *(__half2*)&raw.y;
    float2 f0 = __half22float2(p0), f1 = __half22float2(p1);
    acc.x += f0.x * nm; acc.y += f0.y * nm;
    acc.z += f1.x * nm; acc.w += f1.y * nm;
}

__global__ __launch_bounds__(256) void acc_kernel(const float* __restrict__ b, int n)
{
    __shared__ float ssum[8][128];
    __shared__ float ssq[8][128];
    const int w = (blockIdx.x * blockDim.x + threadIdx.x) >> 5;
    const int wid = threadIdx.x >> 5;
    const int lane = threadIdx.x & 31;

    float4 acc = make_float4(0.f, 0.f, 0.f, 0.f);
    if (w < n) {
        float di = g_dinv[w];
        acc = __ldg((const float4*)b + lane);
        // self loop (norm = dinv^2)
        {
            uint2 raw = __ldg((const uint2*)(g_h + (size_t)w * DIM) + lane);
            fma_row(acc, raw, di * di);
        }
        const int cnt = g_cnt[w];
        const int* bkt = g_bkt + (size_t)w * BCAP;
        int j = 0;
        for (; j + 4 <= cnt; j += 4) {
            int s0 = __ldg(bkt + j);
            int s1 = __ldg(bkt + j + 1);
            int s2 = __ldg(bkt + j + 2);
            int s3 = __ldg(bkt + j + 3);
            float nm0 = di * __ldg(g_dinv + s0);
            float nm1 = di * __ldg(g_dinv + s1);
            float nm2 = di * __ldg(g_dinv + s2);
            float nm3 = di * __ldg(g_dinv + s3);
            uint2 r0 = __ldg((const uint2*)(g_h + (size_t)s0 * DIM) + lane);
            uint2 r1 = __ldg((const uint2*)(g_h + (size_t)s1 * DIM) + lane);
            uint2 r2 = __ldg((const uint2*)(g_h + (size_t)s2 * DIM) + lane);
            uint2 r3 = __ldg((const uint2*)(g_h + (size_t)s3 * DIM) + lane);
            fma_row(acc, r0, nm0);
            fma_row(acc, r1, nm1);
            fma_row(acc, r2, nm2);
            fma_row(acc, r3, nm3);
        }
        for (; j < cnt; j++) {
            int s0 = __ldg(bkt + j);
            float nm0 = di * __ldg(g_dinv + s0);
            uint2 r0 = __ldg((const uint2*)(g_h + (size_t)s0 * DIM) + lane);
            fma_row(acc, r0, nm0);
        }
        // store agg as fp16 (stats below use the fp32 registers)
        uint2 packed;
        *(__half2*)&packed.x = __floats2half2_rn(acc.x, acc.y);
        *(__half2*)&packed.y = __floats2half2_rn(acc.z, acc.w);
        *((uint2*)(g_agg + (size_t)w * DIM) + lane) = packed;
    }
    *(float4*)&ssum[wid][lane * 4] = acc;
    float4 sq = make_float4(acc.x * acc.x, acc.y * acc.y, acc.z * acc.z, acc.w * acc.w);
    *(float4*)&ssq[wid][lane * 4] = sq;
    __syncthreads();

    int t = threadIdx.x;
    if (t < 128) {
        float s = 0.f;
#pragma unroll
        for (int k = 0; k < 8; k++) s += ssum[k][t];
        atomicAdd(&g_stats[t], s);
    } else {
        int d = t - 128;
        float s = 0.f;
#pragma unroll
        for (int k = 0; k < 8; k++) s += ssq[k][d];
        atomicAdd(&g_stats[DIM + d], s);
    }
}

// ---------------- epilogue: finalize fused, relu(BN(agg)) + x ---------
// also re-zeroes g_cnt for the next invocation (globals start zeroed at load)
__global__ __launch_bounds__(256) void out_kernel(
    const float* __restrict__ x, const float* __restrict__ gamma,
    const float* __restrict__ beta, float* __restrict__ out,
    float inv_n, int total4, int n)
{
    __shared__ float ssc[DIM];
    __shared__ float ssh[DIM];
    int t = threadIdx.x;
    if (t < DIM) {
        float mean = g_stats[t] * inv_n;
        float var  = g_stats[DIM + t] * inv_n - mean * mean;
        float sc = gamma[t] * rsqrtf(var + BN_EPS);
        ssc[t] = sc;
        ssh[t] = beta[t] - mean * sc;
    }
    __syncthreads();

    int i = blockIdx.x * blockDim.x + t;
    if (i < n) g_cnt[i] = 0;               // reset for next replay
    if (i >= total4) return;
    int d4 = i & 31;
    uint2 raw = ((const uint2*)g_agg)[i];
    float2 a01 = __half22float2(*(__half2*)&raw.x);
    float2 a23 = __half22float2(*(__half2*)&raw.y);
    float4 sc = *(float4*)&ssc[d4 * 4];
    float4 sh = *(float4*)&ssh[d4 * 4];
    float4 xv = ((const float4*)x)[i];
    float4 y;
    y.x = fmaxf(a01.x * sc.x + sh.x, 0.f) + xv.x;
    y.y = fmaxf(a01.y * sc.y + sh.y, 0.f) + xv.y;
    y.z = fmaxf(a23.x * sc.z + sh.z, 0.f) + xv.z;
    y.w = fmaxf(a23.y * sc.w + sh.w, 0.f) + xv.w;
    ((float4*)out)[i] = y;
}

// ---------------- launch ----------------------------------------------
extern "C" void kernel_launch(void* const* d_in, const int* in_sizes, int n_in,
                              void* d_out, int out_size)
{
    const float* x     = (const float*)d_in[0];
    const float* W     = (const float*)d_in[1];
    const float* b     = (const float*)d_in[2];
    const float* gamma = (const float*)d_in[3];
    const float* beta  = (const float*)d_in[4];
    const int*   ei    = (const int*)d_in[5];

    const int n = in_sizes[0] / DIM;
    const int E = in_sizes[5] / 2;
    const int* src = ei;
    const int* dst = ei + E;

    // fork: GEMM on side stream, overlapping the bucket build
    cudaEventRecord(g_fork.e0, 0);
    cudaStreamWaitEvent(g_fork.s, g_fork.e0, 0);
    gemm_tc_kernel<<<(n + 127) / 128, 256, 0, g_fork.s>>>(x, W, n);
    cudaEventRecord(g_fork.e1, g_fork.s);

    // main chain: single-pass bucket CSR
    fill_kernel<<<(E + 255) / 256, 256>>>(src, dst, E);
    dinv_kernel<<<(n + 255) / 256, 256>>>(n);   // also zeroes stats

    // join: acc needs both g_h (side) and buckets (main)
    cudaStreamWaitEvent(0, g_fork.e1, 0);
    acc_kernel<<<(n + 7) / 8, 256>>>(b, n);

    int total4 = n * DIM / 4;
    out_kernel<<<(total4 + 255) / 256, 256>>>(x, gamma, beta, (float*)d_out,
                                              1.0f / (float)n, total4, n);
}

// round 16
// speedup vs baseline: 1.0175x; 1.0035x over previous
#include <cuda_runtime.h>
#include <cuda_bf16.h>
#include <cuda_fp16.h>
#include <cstdint>

#define N_NODES_MAX 50048
#define E_MAX 1600000
#define DIM 128
#define BCAP 128
#define BN_EPS 1e-5f

// ---------------- device scratch ----------------
__device__ __half g_h[N_NODES_MAX * DIM];     // x @ W in fp16 (gather payload)
__device__ __half g_agg[N_NODES_MAX * DIM];   // aggregated messages (fp16)
__device__ float g_dinv[N_NODES_MAX];
__device__ int   g_cnt[N_NODES_MAX];          // zero at module load; re-zeroed by out_kernel
__device__ int   g_bkt[N_NODES_MAX * BCAP];   // per-node edge buckets
__device__ float g_stats[2 * DIM];

// ---------------- stream/event fork-join resources (static init) ------
struct ForkRes {
    cudaStream_t s;
    cudaEvent_t e0, e1;
    ForkRes() {
        cudaStreamCreateWithFlags(&s, cudaStreamNonBlocking);
        cudaEventCreateWithFlags(&e0, cudaEventDisableTiming);
        cudaEventCreateWithFlags(&e1, cudaEventDisableTiming);
    }
};
static ForkRes g_fork;

// ---------------- bucket fill: single edge pass ----------------
__global__ void fill_kernel(const int* __restrict__ src,
                            const int* __restrict__ dst, int E) {
    int e = blockIdx.x * blockDim.x + threadIdx.x;
    if (e < E) {
        int d = dst[e];
        int pos = atomicAdd(&g_cnt[d], 1);
        if (pos < BCAP)
            g_bkt[(size_t)d * BCAP + pos] = src[e];
    }
}

// ---------------- dinv from counts (+ zero stats for this pass) -------
__global__ void dinv_kernel(int n) {
    int i = blockIdx.x * blockDim.x + threadIdx.x;
    if (i < n) g_dinv[i] = rsqrtf((float)(g_cnt[i] + 1));
    if (i < 2 * DIM) g_stats[i] = 0.0f;
}

// ---------------- single-pass FP16 tensor-core GEMM: h = x @ W --------
// m16n8k16, fp16 in / fp32 accum. Fragment layout validated in R7.
__device__ __forceinline__ void mma_f16(float* c, uint32_t a0, uint32_t a1,
                                        uint32_t a2, uint32_t a3,
                                        uint32_t b0, uint32_t b1) {
    asm volatile(
        "mma.sync.aligned.m16n8k16.row.col.f32.f16.f16.f32 "
        "{%0,%1,%2,%3}, {%4,%5,%6,%7}, {%8,%9}, {%0,%1,%2,%3};"
        : "+f"(c[0]), "+f"(c[1]), "+f"(c[2]), "+f"(c[3])
        : "r"(a0), "r"(a1), "r"(a2), "r"(a3), "r"(b0), "r"(b1));
}

#define KC 32
#define XPAD 40   // row stride in halves (80B)
__global__ __launch_bounds__(256, 2) void gemm_tc_kernel(
    const float* __restrict__ x, const float* __restrict__ W, int n)
{
    __shared__ __half xs[128][XPAD];   // [row][k] chunk
    __shared__ __half wt[128][XPAD];   // transposed: [n][k]

    const int t = threadIdx.x;
    const int wid = t >> 5, lane = t & 31;
    const int rowg = wid & 3, colg = wid >> 2;
    const int g = lane >> 2, t4 = lane & 3;
    const int row0 = blockIdx.x * 128;

    float acc[2][8][4];
#pragma unroll
    for (int mi = 0; mi < 2; mi++)
#pragma unroll
        for (int nt = 0; nt < 8; nt++)
#pragma unroll
            for (int c = 0; c < 4; c++) acc[mi][nt][c] = 0.f;

    for (int kc = 0; kc < DIM; kc += KC) {
        // stage x chunk: 128 rows x 32 k, fp16
        for (int idx = t; idx < 1024; idx += 256) {
            int r = idx >> 3, k4 = (idx & 7) << 2;
            int row = row0 + r;
            float4 v = make_float4(0.f, 0.f, 0.f, 0.f);
            if (row < n) v = *(const float4*)(x + (size_t)row * DIM + kc + k4);
            *(__half2*)&xs[r][k4]     = __floats2half2_rn(v.x, v.y);
            *(__half2*)&xs[r][k4 + 2] = __floats2half2_rn(v.z, v.w);
        }
        // stage W chunk transposed: wt[n][k] = W[kc+k][n], fp16
        for (int idx = t; idx < 1024; idx += 256) {
            int k = idx >> 5, n4 = (idx & 31) << 2;
            float4 v = *(const float4*)(W + (size_t)(kc + k) * DIM + n4);
            wt[n4 + 0][k] = __float2half(v.x);
            wt[n4 + 1][k] = __float2half(v.y);
            wt[n4 + 2][k] = __float2half(v.z);
            wt[n4 + 3][k] = __float2half(v.w);
        }
        __syncthreads();

#pragma unroll
        for (int ks = 0; ks < KC; ks += 16) {
            int k0 = ks + 2 * t4;
            uint32_t a[2][4];
#pragma unroll
            for (int mi = 0; mi < 2; mi++) {
                int rb = rowg * 32 + mi * 16;
                a[mi][0] = *(uint32_t*)&xs[rb + g][k0];
                a[mi][1] = *(uint32_t*)&xs[rb + g + 8][k0];
                a[mi][2] = *(uint32_t*)&xs[rb + g][k0 + 8];
                a[mi][3] = *(uint32_t*)&xs[rb + g + 8][k0 + 8];
            }
#pragma unroll
            for (int nt = 0; nt < 8; nt++) {
                int col = colg * 64 + nt * 8 + g;
                uint32_t b0 = *(uint32_t*)&wt[col][k0];
                uint32_t b1 = *(uint32_t*)&wt[col][k0 + 8];
#pragma unroll
                for (int mi = 0; mi < 2; mi++)
                    mma_f16(acc[mi][nt], a[mi][0], a[mi][1], a[mi][2], a[mi][3], b0, b1);
            }
        }
        __syncthreads();
    }

#pragma unroll
    for (int mi = 0; mi < 2; mi++) {
        int rb = row0 + rowg * 32 + mi * 16;
#pragma unroll
        for (int nt = 0; nt < 8; nt++) {
            int col = colg * 64 + nt * 8 + 2 * t4;
            int r0 = rb + g, r1 = rb + g + 8;
            if (r0 < n)
                *(__half2*)(g_h + (size_t)r0 * DIM + col) =
                    __floats2half2_rn(acc[mi][nt][0], acc[mi][nt][1]);
            if (r1 < n)
                *(__half2*)(g_h + (size_t)r1 * DIM + col) =
                    __floats2half2_rn(acc[mi][nt][2], acc[mi][nt][3]);
        }
    }
}

// ---------------- per-node accumulate + fused BN stats ----------------
__device__ __forceinline__ void fma_row(float4& acc, uint2 raw, float nm) {
    __half2 p0 = *(__half2*)&raw.x, p1 = *(__half2*)&raw.y;
    float2 f0 = __half22float2(p0), f1 = __half22float2(p1);
    acc.x += f0.x * nm; acc.y += f0.y * nm;
    acc.z += f1.x * nm; acc.w += f1.y * nm;
}

__global__ __launch_bounds__(256) void acc_kernel(const float* __restrict__ b, int n)
{
    __shared__ float ssum[8][128];
    __shared__ float ssq[8][128];
    const int w = (blockIdx.x * blockDim.x + threadIdx.x) >> 5;
    const int wid = threadIdx.x >> 5;
    const int lane = threadIdx.x & 31;

    float4 acc = make_float4(0.f, 0.f, 0.f, 0.f);
    if (w < n) {
        float di = g_dinv[w];
        acc = __ldg((const float4*)b + lane);
        // self loop (norm = dinv^2)
        {
            uint2 raw = __ldg((const uint2*)(g_h + (size_t)w * DIM) + lane);
            fma_row(acc, raw, di * di);
        }
        const int cnt = g_cnt[w];
        const int* bkt = g_bkt + (size_t)w * BCAP;
        int j = 0;
        for (; j + 4 <= cnt; j += 4) {
            int s0 = __ldg(bkt + j);
            int s1 = __ldg(bkt + j + 1);
            int s2 = __ldg(bkt + j + 2);
            int s3 = __ldg(bkt + j + 3);
            float nm0 = di * __ldg(g_dinv + s0);
            float nm1 = di * __ldg(g_dinv + s1);
            float nm2 = di * __ldg(g_dinv + s2);
            float nm3 = di * __ldg(g_dinv + s3);
            uint2 r0 = __ldg((const uint2*)(g_h + (size_t)s0 * DIM) + lane);
            uint2 r1 = __ldg((const uint2*)(g_h + (size_t)s1 * DIM) + lane);
            uint2 r2 = __ldg((const uint2*)(g_h + (size_t)s2 * DIM) + lane);
            uint2 r3 = __ldg((const uint2*)(g_h + (size_t)s3 * DIM) + lane);
            fma_row(acc, r0, nm0);
            fma_row(acc, r1, nm1);
            fma_row(acc, r2, nm2);
            fma_row(acc, r3, nm3);
        }
        for (; j < cnt; j++) {
            int s0 = __ldg(bkt + j);
            float nm0 = di * __ldg(g_dinv + s0);
            uint2 r0 = __ldg((const uint2*)(g_h + (size_t)s0 * DIM) + lane);
            fma_row(acc, r0, nm0);
        }
        // store agg as fp16 (stats below use the fp32 registers)
        uint2 packed;
        *(__half2*)&packed.x = __floats2half2_rn(acc.x, acc.y);
        *(__half2*)&packed.y = __floats2half2_rn(acc.z, acc.w);
        *((uint2*)(g_agg + (size_t)w * DIM) + lane) = packed;
    }
    *(float4*)&ssum[wid][lane * 4] = acc;
    float4 sq = make_float4(acc.x * acc.x, acc.y * acc.y, acc.z * acc.z, acc.w * acc.w);
    *(float4*)&ssq[wid][lane * 4] = sq;
    __syncthreads();

    int t = threadIdx.x;
    if (t < 128) {
        float s = 0.f;
#pragma unroll
        for (int k = 0; k < 8; k++) s += ssum[k][t];
        atomicAdd(&g_stats[t], s);
    } else {
        int d = t - 128;
        float s = 0.f;
#pragma unroll
        for (int k = 0; k < 8; k++) s += ssq[k][d];
        atomicAdd(&g_stats[DIM + d], s);
    }
}

// ---------------- epilogue: finalize fused, relu(BN(agg)) + x ---------
// also re-zeroes g_cnt for the next invocation (globals start zeroed at load)
__global__ __launch_bounds__(256) void out_kernel(
    const float* __restrict__ x, const float* __restrict__ gamma,
    const float* __restrict__ beta, float* __restrict__ out,
    float inv_n, int total4, int n)
{
    __shared__ float ssc[DIM];
    __shared__ float ssh[DIM];
    int t = threadIdx.x;
    if (t < DIM) {
        float mean = g_stats[t] * inv_n;
        float var  = g_stats[DIM + t] * inv_n - mean * mean;
        float sc = gamma[t] * rsqrtf(var + BN_EPS);
        ssc[t] = sc;
        ssh[t] = beta[t] - mean * sc;
    }
    __syncthreads();

    int i = blockIdx.x * blockDim.x + t;
    if (i < n) g_cnt[i] = 0;               // reset for next replay
    if (i >= total4) return;
    int d4 = i & 31;
    uint2 raw = ((const uint2*)g_agg)[i];
    float2 a01 = __half22float2(*(__half2*)&raw.x);
    float2 a23 = __half22float2(*(__half2*)&raw.y);
    float4 sc = *(float4*)&ssc[d4 * 4];
    float4 sh = *(float4*)&ssh[d4 * 4];
    float4 xv = ((const float4*)x)[i];
    float4 y;
    y.x = fmaxf(a01.x * sc.x + sh.x, 0.f) + xv.x;
    y.y = fmaxf(a01.y * sc.y + sh.y, 0.f) + xv.y;
    y.z = fmaxf(a23.x * sc.z + sh.z, 0.f) + xv.z;
    y.w = fmaxf(a23.y * sc.w + sh.w, 0.f) + xv.w;
    ((float4*)out)[i] = y;
}

// ---------------- launch ----------------------------------------------
extern "C" void kernel_launch(void* const* d_in, const int* in_sizes, int n_in,
                              void* d_out, int out_size)
{
    const float* x     = (const float*)d_in[0];
    const float* W     = (const float*)d_in[1];
    const float* b     = (const float*)d_in[2];
    const float* gamma = (const float*)d_in[3];
    const float* beta  = (const float*)d_in[4];
    const int*   ei    = (const int*)d_in[5];

    const int n = in_sizes[0] / DIM;
    const int E = in_sizes[5] / 2;
    const int* src = ei;
    const int* dst = ei + E;

    // fork: GEMM on side stream, overlapping the bucket build
    cudaEventRecord(g_fork.e0, 0);
    cudaStreamWaitEvent(g_fork.s, g_fork.e0, 0);
    gemm_tc_kernel<<<(n + 127) / 128, 256, 0, g_fork.s>>>(x, W, n);
    cudaEventRecord(g_fork.e1, g_fork.s);

    // main chain: single-pass bucket CSR
    fill_kernel<<<(E + 255) / 256, 256>>>(src, dst, E);
    dinv_kernel<<<(n + 255) / 256, 256>>>(n);   // also zeroes stats

    // join: acc needs both g_h (side) and buckets (main)
    cudaStreamWaitEvent(0, g_fork.e1, 0);
    acc_kernel<<<(n + 7) / 8, 256>>>(b, n);

    int total4 = n * DIM / 4;
    out_kernel<<<(total4 + 255) / 256, 256>>>(x, gamma, beta, (float*)d_out,
                                              1.0f / (float)n, total4, n);
}

// round 17
// speedup vs baseline: 1.0195x; 1.0020x over previous
#include <cuda_runtime.h>
#include <cuda_bf16.h>
#include <cuda_fp16.h>
#include <cstdint>

#define N_NODES_MAX 50048
#define E_MAX 1600000
#define DIM 128
#define BCAP 128
#define BN_EPS 1e-5f

// ---------------- device scratch ----------------
__device__ __half g_h[N_NODES_MAX * DIM];     // x @ W in fp16 (gather payload)
__device__ __half g_agg[N_NODES_MAX * DIM];   // aggregated messages (fp16)
__device__ float g_dinv[N_NODES_MAX];
__device__ int   g_cnt[N_NODES_MAX];          // zero at module load; re-zeroed by out_kernel
__device__ int   g_bkt[N_NODES_MAX * BCAP];   // per-node edge buckets
__device__ float g_stats[2 * DIM];

// ---------------- stream/event fork-join resources (static init) ------
struct ForkRes {
    cudaStream_t s;
    cudaEvent_t e0, e1;
    ForkRes() {
        cudaStreamCreateWithFlags(&s, cudaStreamNonBlocking);
        cudaEventCreateWithFlags(&e0, cudaEventDisableTiming);
        cudaEventCreateWithFlags(&e1, cudaEventDisableTiming);
    }
};
static ForkRes g_fork;

// ---------------- bucket fill: single edge pass ----------------
__global__ void fill_kernel(const int* __restrict__ src,
                            const int* __restrict__ dst, int E) {
    int e = blockIdx.x * blockDim.x + threadIdx.x;
    if (e < E) {
        int d = dst[e];
        int pos = atomicAdd(&g_cnt[d], 1);
        if (pos < BCAP)
            g_bkt[(size_t)d * BCAP + pos] = src[e];
    }
}

// ---------------- dinv from counts (+ zero stats for this pass) -------
__global__ void dinv_kernel(int n) {
    int i = blockIdx.x * blockDim.x + threadIdx.x;
    if (i < n) g_dinv[i] = rsqrtf((float)(g_cnt[i] + 1));
    if (i < 2 * DIM) g_stats[i] = 0.0f;
}

// ---------------- single-pass FP16 tensor-core GEMM: h = x @ W --------
// m16n8k16, fp16 in / fp32 accum. Fragment layout validated in R7.
__device__ __forceinline__ void mma_f16(float* c, uint32_t a0, uint32_t a1,
                                        uint32_t a2, uint32_t a3,
                                        uint32_t b0, uint32_t b1) {
    asm volatile(
        "mma.sync.aligned.m16n8k16.row.col.f32.f16.f16.f32 "
        "{%0,%1,%2,%3}, {%4,%5,%6,%7}, {%8,%9}, {%0,%1,%2,%3};"
        : "+f"(c[0]), "+f"(c[1]), "+f"(c[2]), "+f"(c[3])
        : "r"(a0), "r"(a1), "r"(a2), "r"(a3), "r"(b0), "r"(b1));
}

#define KC 32
#define XPAD 40   // row stride in halves (80B)
__global__ __launch_bounds__(256, 2) void gemm_tc_kernel(
    const float* __restrict__ x, const float* __restrict__ W, int n)
{
    __shared__ __half xs[128][XPAD];   // [row][k] chunk
    __shared__ __half wt[128][XPAD];   // transposed: [n][k]

    const int t = threadIdx.x;
    const int wid = t >> 5, lane = t & 31;
    const int rowg = wid & 3, colg = wid >> 2;
    const int g = lane >> 2, t4 = lane & 3;
    const int row0 = blockIdx.x * 128;

    float acc[2][8][4];
#pragma unroll
    for (int mi = 0; mi < 2; mi++)
#pragma unroll
        for (int nt = 0; nt < 8; nt++)
#pragma unroll
            for (int c = 0; c < 4; c++) acc[mi][nt][c] = 0.f;

    for (int kc = 0; kc < DIM; kc += KC) {
        // stage x chunk: 128 rows x 32 k, fp16
        for (int idx = t; idx < 1024; idx += 256) {
            int r = idx >> 3, k4 = (idx & 7) << 2;
            int row = row0 + r;
            float4 v = make_float4(0.f, 0.f, 0.f, 0.f);
            if (row < n) v = *(const float4*)(x + (size_t)row * DIM + kc + k4);
            *(__half2*)&xs[r][k4]     = __floats2half2_rn(v.x, v.y);
            *(__half2*)&xs[r][k4 + 2] = __floats2half2_rn(v.z, v.w);
        }
        // stage W chunk transposed: wt[n][k] = W[kc+k][n], fp16
        for (int idx = t; idx < 1024; idx += 256) {
            int k = idx >> 5, n4 = (idx & 31) << 2;
            float4 v = *(const float4*)(W + (size_t)(kc + k) * DIM + n4);
            wt[n4 + 0][k] = __float2half(v.x);
            wt[n4 + 1][k] = __float2half(v.y);
            wt[n4 + 2][k] = __float2half(v.z);
            wt[n4 + 3][k] = __float2half(v.w);
        }
        __syncthreads();

#pragma unroll
        for (int ks = 0; ks < KC; ks += 16) {
            int k0 = ks + 2 * t4;
            uint32_t a[2][4];
#pragma unroll
            for (int mi = 0; mi < 2; mi++) {
                int rb = rowg * 32 + mi * 16;
                a[mi][0] = *(uint32_t*)&xs[rb + g][k0];
                a[mi][1] = *(uint32_t*)&xs[rb + g + 8][k0];
                a[mi][2] = *(uint32_t*)&xs[rb + g][k0 + 8];
                a[mi][3] = *(uint32_t*)&xs[rb + g + 8][k0 + 8];
            }
#pragma unroll
            for (int nt = 0; nt < 8; nt++) {
                int col = colg * 64 + nt * 8 + g;
                uint32_t b0 = *(uint32_t*)&wt[col][k0];
                uint32_t b1 = *(uint32_t*)&wt[col][k0 + 8];
#pragma unroll
                for (int mi = 0; mi < 2; mi++)
                    mma_f16(acc[mi][nt], a[mi][0], a[mi][1], a[mi][2], a[mi][3], b0, b1);
            }
        }
        __syncthreads();
    }

#pragma unroll
    for (int mi = 0; mi < 2; mi++) {
        int rb = row0 + rowg * 32 + mi * 16;
#pragma unroll
        for (int nt = 0; nt < 8; nt++) {
            int col = colg * 64 + nt * 8 + 2 * t4;
            int r0 = rb + g, r1 = rb + g + 8;
            if (r0 < n)
                *(__half2*)(g_h + (size_t)r0 * DIM + col) =
                    __floats2half2_rn(acc[mi][nt][0], acc[mi][nt][1]);
            if (r1 < n)
                *(__half2*)(g_h + (size_t)r1 * DIM + col) =
                    __floats2half2_rn(acc[mi][nt][2], acc[mi][nt][3]);
        }
    }
}

// ---------------- per-node accumulate + fused BN stats ----------------
__device__ __forceinline__ void fma_row(float4& acc, uint2 raw, float nm) {
    __half2 p0 = *(__half2*)&raw.x, p1 = *(__half2*)&raw.y;
    float2 f0 = __half22float2(p0), f1 = __half22float2(p1);
    acc.x += f0.x * nm; acc.y += f0.y * nm;
    acc.z += f1.x * nm; acc.w += f1.y * nm;
}

__global__ __launch_bounds__(256) void acc_kernel(const float* __restrict__ b, int n)
{
    __shared__ float ssum[8][128];
    __shared__ float ssq[8][128];
    const int w = (blockIdx.x * blockDim.x + threadIdx.x) >> 5;
    const int wid = threadIdx.x >> 5;
    const int lane = threadIdx.x & 31;

    float4 acc = make_float4(0.f, 0.f, 0.f, 0.f);
    if (w < n) {
        float di = g_dinv[w];
        acc = __ldg((const float4*)b + lane);
        // self loop (norm = dinv^2)
        {
            uint2 raw = __ldg((const uint2*)(g_h + (size_t)w * DIM) + lane);
            fma_row(acc, raw, di * di);
        }
        const int cnt = g_cnt[w];
        const int* bkt = g_bkt + (size_t)w * BCAP;
        int j = 0;
        if (cnt >= 4) {
            // software-pipelined: batch indices loaded as int4, one batch ahead
            int4 sidx = __ldg((const int4*)bkt);
            for (; j + 4 <= cnt; j += 4) {
                int4 nidx = __ldg((const int4*)(bkt + j + 4));  // prefetch (in-bounds; unused at exit)
                float nm0 = di * __ldg(g_dinv + sidx.x);
                float nm1 = di * __ldg(g_dinv + sidx.y);
                float nm2 = di * __ldg(g_dinv + sidx.z);
                float nm3 = di * __ldg(g_dinv + sidx.w);
                uint2 r0 = __ldg((const uint2*)(g_h + (size_t)sidx.x * DIM) + lane);
                uint2 r1 = __ldg((const uint2*)(g_h + (size_t)sidx.y * DIM) + lane);
                uint2 r2 = __ldg((const uint2*)(g_h + (size_t)sidx.z * DIM) + lane);
                uint2 r3 = __ldg((const uint2*)(g_h + (size_t)sidx.w * DIM) + lane);
                fma_row(acc, r0, nm0);
                fma_row(acc, r1, nm1);
                fma_row(acc, r2, nm2);
                fma_row(acc, r3, nm3);
                sidx = nidx;
            }
        }
        for (; j < cnt; j++) {
            int s0 = __ldg(bkt + j);
            float nm0 = di * __ldg(g_dinv + s0);
            uint2 r0 = __ldg((const uint2*)(g_h + (size_t)s0 * DIM) + lane);
            fma_row(acc, r0, nm0);
        }
        // store agg as fp16 (stats below use the fp32 registers)
        uint2 packed;
        *(__half2*)&packed.x = __floats2half2_rn(acc.x, acc.y);
        *(__half2*)&packed.y = __floats2half2_rn(acc.z, acc.w);
        *((uint2*)(g_agg + (size_t)w * DIM) + lane) = packed;
    }
    *(float4*)&ssum[wid][lane * 4] = acc;
    float4 sq = make_float4(acc.x * acc.x, acc.y * acc.y, acc.z * acc.z, acc.w * acc.w);
    *(float4*)&ssq[wid][lane * 4] = sq;
    __syncthreads();

    int t = threadIdx.x;
    if (t < 128) {
        float s = 0.f;
#pragma unroll
        for (int k = 0; k < 8; k++) s += ssum[k][t];
        atomicAdd(&g_stats[t], s);
    } else {
        int d = t - 128;
        float s = 0.f;
#pragma unroll
        for (int k = 0; k < 8; k++) s += ssq[k][d];
        atomicAdd(&g_stats[DIM + d], s);
    }
}

// ---------------- epilogue: finalize fused, relu(BN(agg)) + x ---------
// also re-zeroes g_cnt for the next invocation (globals start zeroed at load)
__global__ __launch_bounds__(256) void out_kernel(
    const float* __restrict__ x, const float* __restrict__ gamma,
    const float* __restrict__ beta, float* __restrict__ out,
    float inv_n, int total4, int n)
{
    __shared__ float ssc[DIM];
    __shared__ float ssh[DIM];
    int t = threadIdx.x;
    if (t < DIM) {
        float mean = g_stats[t] * inv_n;
        float var  = g_stats[DIM + t] * inv_n - mean * mean;
        float sc = gamma[t] * rsqrtf(var + BN_EPS);
        ssc[t] = sc;
        ssh[t] = beta[t] - mean * sc;
    }
    __syncthreads();

    int i = blockIdx.x * blockDim.x + t;
    if (i < n) g_cnt[i] = 0;               // reset for next replay
    if (i >= total4) return;
    int d4 = i & 31;
    uint2 raw = ((const uint2*)g_agg)[i];
    float2 a01 = __half22float2(*(__half2*)&raw.x);
    float2 a23 = __half22float2(*(__half2*)&raw.y);
    float4 sc = *(float4*)&ssc[d4 * 4];
    float4 sh = *(float4*)&ssh[d4 * 4];
    float4 xv = ((const float4*)x)[i];
    float4 y;
    y.x = fmaxf(a01.x * sc.x + sh.x, 0.f) + xv.x;
    y.y = fmaxf(a01.y * sc.y + sh.y, 0.f) + xv.y;
    y.z = fmaxf(a23.x * sc.z + sh.z, 0.f) + xv.z;
    y.w = fmaxf(a23.y * sc.w + sh.w, 0.f) + xv.w;
    ((float4*)out)[i] = y;
}

// ---------------- launch ----------------------------------------------
extern "C" void kernel_launch(void* const* d_in, const int* in_sizes, int n_in,
                              void* d_out, int out_size)
{
    const float* x     = (const float*)d_in[0];
    const float* W     = (const float*)d_in[1];
    const float* b     = (const float*)d_in[2];
    const float* gamma = (const float*)d_in[3];
    const float* beta  = (const float*)d_in[4];
    const int*   ei    = (const int*)d_in[5];

    const int n = in_sizes[0] / DIM;
    const int E = in_sizes[5] / 2;
    const int* src = ei;
    const int* dst = ei + E;

    // fork: GEMM on side stream, overlapping the bucket build
    cudaEventRecord(g_fork.e0, 0);
    cudaStreamWaitEvent(g_fork.s, g_fork.e0, 0);
    gemm_tc_kernel<<<(n + 127) / 128, 256, 0, g_fork.s>>>(x, W, n);
    cudaEventRecord(g_fork.e1, g_fork.s);

    // main chain: single-pass bucket CSR
    fill_kernel<<<(E + 255) / 256, 256>>>(src, dst, E);
    dinv_kernel<<<(n + 255) / 256, 256>>>(n);   // also zeroes stats

    // join: acc needs both g_h (side) and buckets (main)
    cudaStreamWaitEvent(0, g_fork.e1, 0);
    acc_kernel<<<(n + 7) / 8, 256>>>(b, n);

    int total4 = n * DIM / 4;
    out_kernel<<<(total4 + 255) / 256, 256>>>(x, gamma, beta, (float*)d_out,
                                              1.0f / (float)n, total4, n);
}